// round 1
// baseline (speedup 1.0000x reference)
#include <cuda_runtime.h>
#include <math.h>

// Problem constants
#define NXg 302
#define NYg 394
#define Bb  16
#define Dd  128
#define KK  16
#define UNITS 96               // 6*K
#define NPAIR (NYg/2)          // 197 pairs per row
#define PTS_PER_B (NXg*NPAIR)  // 59494 thread-work-items per batch

// Per-batch, per-component precomputed params: {A1, B1, A2, B2, C2, LC, pad, pad}
__device__ float g_params[Bb][KK][8];

// ---------------------------------------------------------------------------
// Prep kernel: tiny GEMM + softmax-in-log-space + per-component constants.
// One block per batch, 128 threads.
// ---------------------------------------------------------------------------
__global__ void mdn_prep_kernel(const float* __restrict__ inp,
                                const float* __restrict__ w,
                                const float* __restrict__ bias)
{
    __shared__ float s_in[Dd];
    __shared__ float s_y[UNITS];
    const int b = blockIdx.x;
    const int t = threadIdx.x;

    s_in[t] = inp[b * Dd + t];
    __syncthreads();

    if (t < UNITS) {
        float acc = bias[t];
#pragma unroll 8
        for (int d = 0; d < Dd; ++d)
            acc = fmaf(s_in[d], w[d * UNITS + t], acc);
        s_y[t] = acc;
    }
    __syncthreads();

    if (t < KK) {
        const int k = t;
        const float mux = s_y[2 * k];
        const float muy = s_y[2 * k + 1];
        const float a   = s_y[2 * KK + 3 * k];       // sig[...,0]
        const float s22 = s_y[2 * KK + 3 * k + 1];   // L22 = exp(s22)
        const float s11 = s_y[2 * KK + 3 * k + 2];   // L11 = exp(s11)
        const float pik = s_y[5 * KK + k];

        // softmax stats over the 16 pi values (broadcast reads, trivial cost)
        float m = s_y[5 * KK];
        for (int j = 1; j < KK; ++j) m = fmaxf(m, s_y[5 * KK + j]);
        float S = 0.0f;
        for (int j = 0; j < KK; ++j) S += expf(s_y[5 * KK + j] - m);

        const float A1 = expf(-s11);   // 1/L11
        const float A2 = expf(-s22);   // 1/L22
        const float LOG2E    = 1.4426950408889634f;
        const float LOG2_2PI = 2.6514961294723187f;
        // LC = log2( softmax_k / (2*pi*L11*L22) )
        const float LC = (pik - m - s11 - s22) * LOG2E - log2f(S) - LOG2_2PI;

        float* P = g_params[b][k];
        P[0] = A1;
        P[1] = -mux * A1;
        P[2] = A2;
        P[3] = -muy * A2;
        P[4] = -a * A2;
        P[5] = LC;
        P[6] = 0.0f;
        P[7] = 0.0f;
    }
}

// ---------------------------------------------------------------------------
// Fast exp2 on the FMA/ALU pipes only (no MUFU).
// Valid for x in [-126, ~30]; callers clamp at -120.
// Max relative error ~2e-6 (degree-5 Taylor on |f|<=0.5).
// ---------------------------------------------------------------------------
__device__ __forceinline__ float fexp2(float x)
{
    const float MAGIC = 12582912.0f;              // 1.5 * 2^23
    float z = x + MAGIC;                          // round-to-nearest integer
    float f = x - (z - MAGIC);                    // frac in [-0.5, 0.5]
    int   n = __float_as_int(z) - __float_as_int(MAGIC);   // = round(x)
    float p =            1.3333558e-3f;
    p = fmaf(p, f,       9.6181291e-3f);
    p = fmaf(p, f,       5.5504109e-2f);
    p = fmaf(p, f,       2.4022651e-1f);
    p = fmaf(p, f,       6.9314718e-1f);
    p = fmaf(p, f,       1.0f);
    return __int_as_float(__float_as_int(p) + (n << 23));
}

// ---------------------------------------------------------------------------
// Main kernel: one thread evaluates 2 adjacent grid points (same x row ->
// shared z1, z1^2, W per component). Weight + normalizer folded into the
// exponent, so the inner body is pure FFMA + one FMNMX + exp2 splice.
// ---------------------------------------------------------------------------
__global__ __launch_bounds__(256) void mdn_eval_kernel(float* __restrict__ out)
{
    __shared__ float4 sp[2 * KK];   // {A1,B1,A2,B2} , {C2,LC,_,_} per k

    const int b = blockIdx.y;
    const int t = threadIdx.x;
    if (t < 2 * KK)
        sp[t] = reinterpret_cast<const float4*>(g_params[b])[t];
    __syncthreads();

    const int p = blockIdx.x * blockDim.x + t;
    if (p >= PTS_PER_B) return;

    const int i  = p / NPAIR;
    const int jp = p - i * NPAIR;
    const int j  = 2 * jp;

    const float x  = (float)i * (1.0f / (NXg - 1));
    const float y0 = (float)j * (1.0f / (NYg - 1));
    const float y1 = (float)(j + 1) * (1.0f / (NYg - 1));

    const float K2E = -0.7213475204444817f;   // -0.5 * log2(e)

    float acc0 = 0.0f, acc1 = 0.0f;
#pragma unroll
    for (int k = 0; k < KK; ++k) {
        const float4 q0 = sp[2 * k];
        const float4 q1 = sp[2 * k + 1];

        const float z1   = fmaf(x, q0.x, q0.y);     // (x - mux)/L11
        const float z1sq = z1 * z1;
        const float W    = fmaf(q1.x, z1, q0.w);    // -a*z1/L22 - muy/L22

        const float z2a = fmaf(y0, q0.z, W);
        const float z2b = fmaf(y1, q0.z, W);

        const float m0 = fmaf(z2a, z2a, z1sq);      // maha
        const float m1 = fmaf(z2b, z2b, z1sq);

        const float a0 = fmaxf(fmaf(m0, K2E, q1.y), -120.0f);
        const float a1 = fmaxf(fmaf(m1, K2E, q1.y), -120.0f);

        acc0 += fexp2(a0);
        acc1 += fexp2(a1);
    }

    // out element index = b*NX*NY + i*NY + j ; as float2: b*PTS_PER_B + p
    reinterpret_cast<float2*>(out)[(size_t)b * PTS_PER_B + p] =
        make_float2(acc0, acc1);
}

// ---------------------------------------------------------------------------
extern "C" void kernel_launch(void* const* d_in, const int* in_sizes, int n_in,
                              void* d_out, int out_size)
{
    const float* inp  = (const float*)d_in[0];   // [16,128]
    const float* w    = (const float*)d_in[1];   // [128,96]
    const float* bias = (const float*)d_in[2];   // [96]
    float* out = (float*)d_out;                  // [16,302,394,1]

    mdn_prep_kernel<<<Bb, Dd>>>(inp, w, bias);

    dim3 grid((PTS_PER_B + 255) / 256, Bb);
    mdn_eval_kernel<<<grid, 256>>>(out);
}

// round 2
// speedup vs baseline: 1.0215x; 1.0215x over previous
#include <cuda_runtime.h>
#include <math.h>

// Problem constants
#define NXg 302
#define NYg 394
#define Bb  16
#define Dd  128
#define KK  16
#define UNITS 96
#define NPAIR 197              // NY/2 column pairs
#define RPAIR 151              // NX/2 row pairs
#define WPB (RPAIR * NPAIR)    // 29747 work items (2x2 tiles) per batch

// Per-batch, per-component precomputed params: {A1, B1, A2, B2, C2, LC, pad, pad}
__device__ float g_params[Bb][KK][8];

typedef unsigned long long u64;

// ---------------------------------------------------------------------------
// Prep kernel: tiny GEMM + softmax-in-log-space + per-component constants.
// ---------------------------------------------------------------------------
__global__ void mdn_prep_kernel(const float* __restrict__ inp,
                                const float* __restrict__ w,
                                const float* __restrict__ bias)
{
    __shared__ float s_in[Dd];
    __shared__ float s_y[UNITS];
    const int b = blockIdx.x;
    const int t = threadIdx.x;

    s_in[t] = inp[b * Dd + t];
    __syncthreads();

    if (t < UNITS) {
        float acc = bias[t];
#pragma unroll 8
        for (int d = 0; d < Dd; ++d)
            acc = fmaf(s_in[d], w[d * UNITS + t], acc);
        s_y[t] = acc;
    }
    __syncthreads();

    if (t < KK) {
        const int k = t;
        const float mux = s_y[2 * k];
        const float muy = s_y[2 * k + 1];
        const float a   = s_y[2 * KK + 3 * k];
        const float s22 = s_y[2 * KK + 3 * k + 1];
        const float s11 = s_y[2 * KK + 3 * k + 2];
        const float pik = s_y[5 * KK + k];

        float m = s_y[5 * KK];
        for (int j = 1; j < KK; ++j) m = fmaxf(m, s_y[5 * KK + j]);
        float S = 0.0f;
        for (int j = 0; j < KK; ++j) S += expf(s_y[5 * KK + j] - m);

        const float A1 = expf(-s11);
        const float A2 = expf(-s22);
        const float LOG2E    = 1.4426950408889634f;
        const float LOG2_2PI = 2.6514961294723187f;
        const float LC = (pik - m - s11 - s22) * LOG2E - log2f(S) - LOG2_2PI;

        float* P = g_params[b][k];
        P[0] = A1;
        P[1] = -mux * A1;
        P[2] = A2;
        P[3] = -muy * A2;
        P[4] = -a * A2;
        P[5] = LC;
        P[6] = 0.0f;
        P[7] = 0.0f;
    }
}

// ---------------------------------------------------------------------------
// f32x2 packed helpers (sm_103a dual-fp32 pipe)
// ---------------------------------------------------------------------------
__device__ __forceinline__ u64 pack2f(float lo, float hi) {
    u64 d; asm("mov.b64 %0, {%1, %2};" : "=l"(d) : "f"(lo), "f"(hi)); return d;
}
__device__ __forceinline__ u64 pack2i(unsigned lo, unsigned hi) {
    u64 d; asm("mov.b64 %0, {%1, %2};" : "=l"(d) : "r"(lo), "r"(hi)); return d;
}
__device__ __forceinline__ void unpack2i(u64 s, unsigned& lo, unsigned& hi) {
    asm("mov.b64 {%0, %1}, %2;" : "=r"(lo), "=r"(hi) : "l"(s));
}
__device__ __forceinline__ u64 f2fma(u64 a, u64 b, u64 c) {
    u64 d; asm("fma.rn.f32x2 %0, %1, %2, %3;" : "=l"(d) : "l"(a), "l"(b), "l"(c)); return d;
}
__device__ __forceinline__ u64 f2add(u64 a, u64 b) {
    u64 d; asm("add.rn.f32x2 %0, %1, %2;" : "=l"(d) : "l"(a), "l"(b)); return d;
}
__device__ __forceinline__ u64 f2mul(u64 a, u64 b) {
    u64 d; asm("mul.rn.f32x2 %0, %1, %2;" : "=l"(d) : "l"(a), "l"(b)); return d;
}

// Packed exp2 for a pair of args (each <= ~0, clamped at -120 via integer max).
// MAGIC low 9 bits are zero, so n<<23 == bits(z)<<23 (mod 2^32); clamp bits(z).
struct Exp2Consts {
    u64 MAGICP, NMAGICP, NONEP, C5, C4, C3, C2, C1, C0, K2EP;
};

__device__ __forceinline__ u64 exp2p(u64 ap, const Exp2Consts& E)
{
    u64 zp = f2add(ap, E.MAGICP);            // z = a + MAGIC  (round)
    u64 tp = f2add(zp, E.NMAGICP);           // t = z - MAGIC  (= n exactly)
    u64 fp = f2fma(tp, E.NONEP, ap);         // f = a - n, |f|<=0.5
    u64 pp = f2fma(E.C5, fp, E.C4);
    pp = f2fma(pp, fp, E.C3);
    pp = f2fma(pp, fp, E.C2);
    pp = f2fma(pp, fp, E.C1);
    pp = f2fma(pp, fp, E.C0);
    unsigned z0, z1, p0, p1;
    unpack2i(zp, z0, z1);
    unpack2i(pp, p0, p1);
    int n0 = max((int)z0, 0x4B3FFF88);       // = bits(MAGIC) - 120
    int n1 = max((int)z1, 0x4B3FFF88);
    unsigned r0 = p0 + ((unsigned)n0 << 23); // exponent splice
    unsigned r1 = p1 + ((unsigned)n1 << 23);
    return pack2i(r0, r1);
}

// ---------------------------------------------------------------------------
// Main kernel: one thread evaluates a 2x2 tile of grid points.
// Column pair packed into f32x2 lanes; two row streams for ILP.
// ---------------------------------------------------------------------------
__global__ __launch_bounds__(256) void mdn_eval_kernel(float* __restrict__ out)
{
    // duplicated packed params: [k][{A1,B1,A2,B2,C2,LC}] as {v,v} pairs
    __shared__ float2 sp[KK * 6];

    const int b = blockIdx.y;
    const int t = threadIdx.x;
    if (t < KK * 6) {
        const int k = t / 6, c = t % 6;
        const float v = g_params[b][k][c];
        sp[t] = make_float2(v, v);
    }
    __syncthreads();

    const int p = blockIdx.x * 256 + t;
    if (p >= WPB) return;

    const int rp = p / NPAIR;
    const int jp = p - rp * NPAIR;

    const float x0 = (float)(2 * rp)     * (1.0f / (NXg - 1));
    const float x1 = (float)(2 * rp + 1) * (1.0f / (NXg - 1));
    const float y0 = (float)(2 * jp)     * (1.0f / (NYg - 1));
    const float y1 = (float)(2 * jp + 1) * (1.0f / (NYg - 1));

    const u64 xp0 = pack2f(x0, x0);
    const u64 xp1 = pack2f(x1, x1);
    const u64 yp  = pack2f(y0, y1);

    Exp2Consts E;
    E.MAGICP  = 0x4B4000004B400000ULL;   // {12582912.f, 12582912.f}
    E.NMAGICP = 0xCB400000CB400000ULL;   // {-12582912.f, ...}
    E.NONEP   = 0xBF800000BF800000ULL;   // {-1.f, -1.f}
    E.C5 = pack2f(1.3333558e-3f, 1.3333558e-3f);
    E.C4 = pack2f(9.6181291e-3f, 9.6181291e-3f);
    E.C3 = pack2f(5.5504109e-2f, 5.5504109e-2f);
    E.C2 = pack2f(2.4022651e-1f, 2.4022651e-1f);
    E.C1 = pack2f(6.9314718e-1f, 6.9314718e-1f);
    E.C0 = 0x3F8000003F800000ULL;        // {1.f, 1.f}
    const u64 K2EP = pack2f(-0.7213475204444817f, -0.7213475204444817f);

    u64 acc0 = 0ULL;   // {0.f, 0.f}
    u64 acc1 = 0ULL;

    const u64* spp = reinterpret_cast<const u64*>(sp);

#pragma unroll
    for (int k = 0; k < KK; ++k) {
        const u64 A1p = spp[k * 6 + 0];
        const u64 B1p = spp[k * 6 + 1];
        const u64 A2p = spp[k * 6 + 2];
        const u64 B2p = spp[k * 6 + 3];
        const u64 C2p = spp[k * 6 + 4];
        const u64 LCp = spp[k * 6 + 5];

        // row stream 0
        {
            u64 z1  = f2fma(xp0, A1p, B1p);
            u64 z1s = f2mul(z1, z1);
            u64 W   = f2fma(C2p, z1, B2p);
            u64 z2  = f2fma(yp, A2p, W);
            u64 m   = f2fma(z2, z2, z1s);
            u64 a   = f2fma(m, K2EP, LCp);
            acc0 = f2add(acc0, exp2p(a, E));
        }
        // row stream 1
        {
            u64 z1  = f2fma(xp1, A1p, B1p);
            u64 z1s = f2mul(z1, z1);
            u64 W   = f2fma(C2p, z1, B2p);
            u64 z2  = f2fma(yp, A2p, W);
            u64 m   = f2fma(z2, z2, z1s);
            u64 a   = f2fma(m, K2EP, LCp);
            acc1 = f2add(acc1, exp2p(a, E));
        }
    }

    // out[b][i][j]: float2 index = (b*NX + i)*NPAIR + jp
    u64* o64 = reinterpret_cast<u64*>(out);
    const size_t o0 = (size_t)(b * NXg + 2 * rp) * NPAIR + jp;
    o64[o0]         = acc0;   // row 2*rp,   cols (2jp, 2jp+1)
    o64[o0 + NPAIR] = acc1;   // row 2*rp+1
}

// ---------------------------------------------------------------------------
extern "C" void kernel_launch(void* const* d_in, const int* in_sizes, int n_in,
                              void* d_out, int out_size)
{
    const float* inp  = (const float*)d_in[0];   // [16,128]
    const float* w    = (const float*)d_in[1];   // [128,96]
    const float* bias = (const float*)d_in[2];   // [96]
    float* out = (float*)d_out;                  // [16,302,394,1]

    mdn_prep_kernel<<<Bb, Dd>>>(inp, w, bias);

    dim3 grid((WPB + 255) / 256, Bb);
    mdn_eval_kernel<<<grid, 256>>>(out);
}

// round 3
// speedup vs baseline: 1.3506x; 1.3222x over previous
#include <cuda_runtime.h>
#include <math.h>

// Problem constants
#define NXg 302
#define NYg 394
#define Bb  16
#define Dd  128
#define KK  16
#define UNITS 96
#define SPR  25                 // strips per row (16 pts each; last has 10)
#define WPBATCH (NXg * SPR)     // 7550 strip-threads per batch
#define TPB 256
#define BPBATCH ((WPBATCH + TPB - 1) / TPB)   // 30

typedef unsigned long long u64;

// Per-batch, per-component packed-duplicated params:
// [b][k][10] float2 {v,v}: 0:A1 1:B1 2:A2 3:B2 4:C2 5:LC 6:G1 7:G0 8:c 9:pad
__device__ float2 g_pp[Bb][KK][10];

// ---------------------------------------------------------------------------
// Prep kernel: tiny GEMM + softmax-in-log-space + per-component constants.
// ---------------------------------------------------------------------------
__global__ void mdn_prep_kernel(const float* __restrict__ inp,
                                const float* __restrict__ w,
                                const float* __restrict__ bias)
{
    __shared__ float s_in[Dd];
    __shared__ float s_y[UNITS];
    const int b = blockIdx.x;
    const int t = threadIdx.x;

    s_in[t] = inp[b * Dd + t];
    __syncthreads();

    if (t < UNITS) {
        float acc = bias[t];
#pragma unroll 8
        for (int d = 0; d < Dd; ++d)
            acc = fmaf(s_in[d], w[d * UNITS + t], acc);
        s_y[t] = acc;
    }
    __syncthreads();

    if (t < KK) {
        const int k = t;
        const float mux = s_y[2 * k];
        const float muy = s_y[2 * k + 1];
        const float a   = s_y[2 * KK + 3 * k];
        const float s22 = s_y[2 * KK + 3 * k + 1];
        const float s11 = s_y[2 * KK + 3 * k + 2];
        const float pik = s_y[5 * KK + k];

        float m = s_y[5 * KK];
        for (int j = 1; j < KK; ++j) m = fmaxf(m, s_y[5 * KK + j]);
        float S = 0.0f;
        for (int j = 0; j < KK; ++j) S += expf(s_y[5 * KK + j] - m);

        const float A1 = expf(-s11);
        const float A2 = expf(-s22);
        const float LOG2E    = 1.4426950408889634f;
        const float LOG2_2PI = 2.6514961294723187f;
        const float K2E      = -0.7213475204444817f;   // -0.5*log2(e)
        const float LC = (pik - m - s11 - s22) * LOG2E - log2f(S) - LOG2_2PI;

        const float dyv = 1.0f / (NYg - 1);
        const float Sstep = 2.0f * A2 * dyv;          // z2 step for dj=2
        const float G1 = 2.0f * K2E * Sstep;
        const float G0 = K2E * Sstep * Sstep;
        const float c  = exp2f(G1 * Sstep);           // ratio of ratios (<1)

        float2* P = g_pp[b][k];
        P[0] = make_float2(A1, A1);
        P[1] = make_float2(-mux * A1, -mux * A1);
        P[2] = make_float2(A2, A2);
        P[3] = make_float2(-muy * A2, -muy * A2);
        P[4] = make_float2(-a * A2, -a * A2);
        P[5] = make_float2(LC, LC);
        P[6] = make_float2(G1, G1);
        P[7] = make_float2(G0, G0);
        P[8] = make_float2(c, c);
        P[9] = make_float2(0.0f, 0.0f);
    }
}

// ---------------------------------------------------------------------------
// f32x2 packed helpers
// ---------------------------------------------------------------------------
__device__ __forceinline__ u64 pack2f(float lo, float hi) {
    u64 d; asm("mov.b64 %0, {%1, %2};" : "=l"(d) : "f"(lo), "f"(hi)); return d;
}
__device__ __forceinline__ u64 pack2i(unsigned lo, unsigned hi) {
    u64 d; asm("mov.b64 %0, {%1, %2};" : "=l"(d) : "r"(lo), "r"(hi)); return d;
}
__device__ __forceinline__ void unpack2i(u64 s, unsigned& lo, unsigned& hi) {
    asm("mov.b64 {%0, %1}, %2;" : "=r"(lo), "=r"(hi) : "l"(s));
}
__device__ __forceinline__ u64 f2fma(u64 a, u64 b, u64 c) {
    u64 d; asm("fma.rn.f32x2 %0, %1, %2, %3;" : "=l"(d) : "l"(a), "l"(b), "l"(c)); return d;
}
__device__ __forceinline__ u64 f2add(u64 a, u64 b) {
    u64 d; asm("add.rn.f32x2 %0, %1, %2;" : "=l"(d) : "l"(a), "l"(b)); return d;
}
__device__ __forceinline__ u64 f2mul(u64 a, u64 b) {
    u64 d; asm("mul.rn.f32x2 %0, %1, %2;" : "=l"(d) : "l"(a), "l"(b)); return d;
}

#define MAGICP  0x4B4000004B400000ULL
#define NMAGICP 0xCB400000CB400000ULL
#define NONEP   0xBF800000BF800000ULL
#define C0P     0x3F8000003F800000ULL
#define BITS_LO_E 0x4B3FFF88   // bits(MAGIC) - 120
#define BITS_LO_R 0x4B3FFFFA   // bits(MAGIC) - 6
#define BITS_HI_R 0x4B400006   // bits(MAGIC) + 6

struct PolyC { u64 C5, C4, C3, C2, C1, K2EP; };

// shared poly core: returns pp and leaves zbits in z0/z1
__device__ __forceinline__ u64 exp2_core(u64 ap, const PolyC& P,
                                         unsigned& z0, unsigned& z1)
{
    u64 zp = f2add(ap, MAGICP);
    u64 tp = f2add(zp, NMAGICP);
    u64 fp = f2fma(tp, NONEP, ap);          // f = a - round(a), |f|<=0.5 always
    u64 pp = f2fma(P.C5, fp, P.C4);
    pp = f2fma(pp, fp, P.C3);
    pp = f2fma(pp, fp, P.C2);
    pp = f2fma(pp, fp, P.C1);
    pp = f2fma(pp, fp, C0P);
    unpack2i(zp, z0, z1);
    return pp;
}

// exp2 with lower clamp at 2^-120 (for E_start)
__device__ __forceinline__ u64 exp2E(u64 ap, const PolyC& P)
{
    unsigned z0, z1, p0, p1;
    u64 pp = exp2_core(ap, P, z0, z1);
    unpack2i(pp, p0, p1);
    int n0 = max((int)z0, (int)BITS_LO_E);
    int n1 = max((int)z1, (int)BITS_LO_E);
    return pack2i(p0 + ((unsigned)n0 << 23), p1 + ((unsigned)n1 << 23));
}

// exp2 with n clamped to [-6, +6] (for the step ratio r)
__device__ __forceinline__ u64 exp2R(u64 ap, const PolyC& P)
{
    unsigned z0, z1, p0, p1;
    u64 pp = exp2_core(ap, P, z0, z1);
    unpack2i(pp, p0, p1);
    int n0 = min(max((int)z0, (int)BITS_LO_R), (int)BITS_HI_R);
    int n1 = min(max((int)z1, (int)BITS_LO_R), (int)BITS_HI_R);
    return pack2i(p0 + ((unsigned)n0 << 23), p1 + ((unsigned)n1 << 23));
}

// ---------------------------------------------------------------------------
// Eval kernel: one thread = one 16-point strip of one row (8 packed pairs).
// Per k: exact exp2 anchor + geometric recurrence along the strip.
// ---------------------------------------------------------------------------
__global__ __launch_bounds__(TPB) void mdn_eval_kernel(float* __restrict__ out)
{
    __shared__ u64 sp[KK * 10];    // packed-dup params for this batch

    const int b = blockIdx.y;
    const int t = threadIdx.x;
    if (t < KK * 10)
        sp[t] = reinterpret_cast<const u64*>(g_pp[b])[t];
    __syncthreads();

    const int wi = blockIdx.x * TPB + t;
    if (wi >= WPBATCH) return;

    const int i     = wi / SPR;
    const int strip = wi - i * SPR;
    const int j0    = strip * 16;

    const float x  = (float)i * (1.0f / (NXg - 1));
    const float y0 = (float)j0 * (1.0f / (NYg - 1));
    const float y1 = (float)(j0 + 1) * (1.0f / (NYg - 1));

    const u64 xp = pack2f(x, x);
    const u64 yp = pack2f(y0, y1);

    PolyC P;
    P.C5 = pack2f(1.3333558e-3f, 1.3333558e-3f);
    P.C4 = pack2f(9.6181291e-3f, 9.6181291e-3f);
    P.C3 = pack2f(5.5504109e-2f, 5.5504109e-2f);
    P.C2 = pack2f(2.4022651e-1f, 2.4022651e-1f);
    P.C1 = pack2f(6.9314718e-1f, 6.9314718e-1f);
    P.K2EP = pack2f(-0.7213475204444817f, -0.7213475204444817f);

    u64 acc[8];
#pragma unroll
    for (int n = 0; n < 8; ++n) acc[n] = 0ULL;

#pragma unroll
    for (int k = 0; k < KK; ++k) {
        const ulonglong2 q0 = *reinterpret_cast<const ulonglong2*>(&sp[k * 10 + 0]); // A1,B1
        const ulonglong2 q1 = *reinterpret_cast<const ulonglong2*>(&sp[k * 10 + 2]); // A2,B2
        const ulonglong2 q2 = *reinterpret_cast<const ulonglong2*>(&sp[k * 10 + 4]); // C2,LC
        const ulonglong2 q3 = *reinterpret_cast<const ulonglong2*>(&sp[k * 10 + 6]); // G1,G0
        const u64 cP = sp[k * 10 + 8];

        u64 z1  = f2fma(xp, q0.x, q0.y);
        u64 z1s = f2mul(z1, z1);
        u64 W   = f2fma(q2.x, z1, q1.y);
        u64 z2  = f2fma(yp, q1.x, W);
        u64 m   = f2fma(z2, z2, z1s);
        u64 a0  = f2fma(m, P.K2EP, q2.y);
        u64 E   = exp2E(a0, P);
        u64 dq  = f2fma(z2, q3.x, q3.y);
        u64 r   = exp2R(dq, P);

        acc[0] = f2add(acc[0], E);
#pragma unroll
        for (int n = 1; n < 8; ++n) {
            E = f2mul(E, r);
            if (n < 7) r = f2mul(r, cP);
            acc[n] = f2add(acc[n], E);
        }
    }

    // store: pair n -> columns (j0+2n, j0+2n+1) of row i
    u64* o64 = reinterpret_cast<u64*>(out);
    const size_t base = (size_t)(b * NXg + i) * (NYg / 2) + (j0 >> 1);
    const int npairs = min(8, (NYg - j0) >> 1);   // 8 normally, 5 on last strip
#pragma unroll
    for (int n = 0; n < 8; ++n)
        if (n < npairs) o64[base + n] = acc[n];
}

// ---------------------------------------------------------------------------
extern "C" void kernel_launch(void* const* d_in, const int* in_sizes, int n_in,
                              void* d_out, int out_size)
{
    const float* inp  = (const float*)d_in[0];   // [16,128]
    const float* w    = (const float*)d_in[1];   // [128,96]
    const float* bias = (const float*)d_in[2];   // [96]
    float* out = (float*)d_out;                  // [16,302,394,1]

    mdn_prep_kernel<<<Bb, Dd>>>(inp, w, bias);

    dim3 grid(BPBATCH, Bb);
    mdn_eval_kernel<<<grid, TPB>>>(out);
}

// round 4
// speedup vs baseline: 1.5351x; 1.1366x over previous
#include <cuda_runtime.h>
#include <math.h>

// Problem constants
#define NXg 302
#define NYg 394
#define Bb  16
#define Dd  128
#define KK  16
#define UNITS 96
#define SPR  25                 // strips per row (16 pts each; last has 10)
#define WPBATCH (NXg * SPR)     // 7550 strips per batch
#define TPB 128
#define BPBATCH ((WPBATCH * 2 + TPB - 1) / TPB)   // 118 (2 threads per strip)

typedef unsigned long long u64;

// ---------------------------------------------------------------------------
// f32x2 packed helpers
// ---------------------------------------------------------------------------
__device__ __forceinline__ u64 pack2f(float lo, float hi) {
    u64 d; asm("mov.b64 %0, {%1, %2};" : "=l"(d) : "f"(lo), "f"(hi)); return d;
}
__device__ __forceinline__ u64 pack2i(unsigned lo, unsigned hi) {
    u64 d; asm("mov.b64 %0, {%1, %2};" : "=l"(d) : "r"(lo), "r"(hi)); return d;
}
__device__ __forceinline__ void unpack2i(u64 s, unsigned& lo, unsigned& hi) {
    asm("mov.b64 {%0, %1}, %2;" : "=r"(lo), "=r"(hi) : "l"(s));
}
__device__ __forceinline__ u64 f2fma(u64 a, u64 b, u64 c) {
    u64 d; asm("fma.rn.f32x2 %0, %1, %2, %3;" : "=l"(d) : "l"(a), "l"(b), "l"(c)); return d;
}
__device__ __forceinline__ u64 f2add(u64 a, u64 b) {
    u64 d; asm("add.rn.f32x2 %0, %1, %2;" : "=l"(d) : "l"(a), "l"(b)); return d;
}
__device__ __forceinline__ u64 f2mul(u64 a, u64 b) {
    u64 d; asm("mul.rn.f32x2 %0, %1, %2;" : "=l"(d) : "l"(a), "l"(b)); return d;
}

#define MAGICP  0x4B4000004B400000ULL
#define NMAGICP 0xCB400000CB400000ULL
#define NONEP   0xBF800000BF800000ULL
#define C0P     0x3F8000003F800000ULL
#define BITS_LO_E 0x4B3FFF88   // bits(MAGIC) - 120
#define BITS_LO_R 0x4B3FFFFA   // bits(MAGIC) - 6
#define BITS_HI_R 0x4B400006   // bits(MAGIC) + 6

struct PolyC { u64 C5, C4, C3, C2, C1, K2EP; };

__device__ __forceinline__ u64 exp2_core(u64 ap, const PolyC& P,
                                         unsigned& z0, unsigned& z1)
{
    u64 zp = f2add(ap, MAGICP);
    u64 tp = f2add(zp, NMAGICP);
    u64 fp = f2fma(tp, NONEP, ap);          // f = a - round(a), |f|<=0.5
    u64 pp = f2fma(P.C5, fp, P.C4);
    pp = f2fma(pp, fp, P.C3);
    pp = f2fma(pp, fp, P.C2);
    pp = f2fma(pp, fp, P.C1);
    pp = f2fma(pp, fp, C0P);
    unpack2i(zp, z0, z1);
    return pp;
}

// exp2 with lower clamp at 2^-120 (anchor E)
__device__ __forceinline__ u64 exp2E(u64 ap, const PolyC& P)
{
    unsigned z0, z1, p0, p1;
    u64 pp = exp2_core(ap, P, z0, z1);
    unpack2i(pp, p0, p1);
    int n0 = max((int)z0, (int)BITS_LO_E);
    int n1 = max((int)z1, (int)BITS_LO_E);
    return pack2i(p0 + ((unsigned)n0 << 23), p1 + ((unsigned)n1 << 23));
}

// exp2 with n clamped to [-6, +6] (step ratio r; only fires in dead zones)
__device__ __forceinline__ u64 exp2R(u64 ap, const PolyC& P)
{
    unsigned z0, z1, p0, p1;
    u64 pp = exp2_core(ap, P, z0, z1);
    unpack2i(pp, p0, p1);
    int n0 = min(max((int)z0, (int)BITS_LO_R), (int)BITS_HI_R);
    int n1 = min(max((int)z1, (int)BITS_LO_R), (int)BITS_HI_R);
    return pack2i(p0 + ((unsigned)n0 << 23), p1 + ((unsigned)n1 << 23));
}

// ---------------------------------------------------------------------------
// Fused kernel. Prologue: per-block redundant GEMM + softmax + param derivation
// (w stays hot in L1 across blocks on the same SM within the launch).
// Main: thread pair (even/odd lane) splits the 16 components over one
// 16-point strip; geometric recurrence along the strip; shfl-combine.
// ---------------------------------------------------------------------------
__global__ __launch_bounds__(TPB) void mdn_fused_kernel(
    const float* __restrict__ inp,
    const float* __restrict__ w,
    const float* __restrict__ bias,
    float* __restrict__ out)
{
    __shared__ float s_in[Dd];
    __shared__ float s_y[UNITS];
    __shared__ u64 sp[KK * 10];   // packed-dup params

    const int b = blockIdx.y;
    const int t = threadIdx.x;

    s_in[t] = inp[b * Dd + t];
    __syncthreads();

    if (t < UNITS) {
        float acc = bias[t];
#pragma unroll 16
        for (int d = 0; d < Dd; ++d)
            acc = fmaf(s_in[d], w[d * UNITS + t], acc);
        s_y[t] = acc;
    }
    __syncthreads();

    if (t < KK) {
        const int k = t;
        const float mux = s_y[2 * k];
        const float muy = s_y[2 * k + 1];
        const float aa  = s_y[2 * KK + 3 * k];
        const float s22 = s_y[2 * KK + 3 * k + 1];
        const float s11 = s_y[2 * KK + 3 * k + 2];
        const float pik = s_y[5 * KK + k];

        float m = s_y[5 * KK];
        for (int j = 1; j < KK; ++j) m = fmaxf(m, s_y[5 * KK + j]);
        float S = 0.0f;
        for (int j = 0; j < KK; ++j) S += expf(s_y[5 * KK + j] - m);

        const float A1 = expf(-s11);
        const float A2 = expf(-s22);
        const float LOG2E    = 1.4426950408889634f;
        const float LOG2_2PI = 2.6514961294723187f;
        const float K2E      = -0.7213475204444817f;   // -0.5*log2(e)
        const float LC = (pik - m - s11 - s22) * LOG2E - log2f(S) - LOG2_2PI;

        const float dyv = 1.0f / (NYg - 1);
        const float Sstep = 2.0f * A2 * dyv;           // z2 step for dj=2
        const float G1 = 2.0f * K2E * Sstep;
        const float G0 = K2E * Sstep * Sstep;
        const float c  = exp2f(G1 * Sstep);            // ratio of ratios

        u64* P = &sp[k * 10];
        P[0] = pack2f(A1, A1);
        P[1] = pack2f(-mux * A1, -mux * A1);
        P[2] = pack2f(A2, A2);
        P[3] = pack2f(-muy * A2, -muy * A2);
        P[4] = pack2f(-aa * A2, -aa * A2);
        P[5] = pack2f(LC, LC);
        P[6] = pack2f(G1, G1);
        P[7] = pack2f(G0, G0);
        P[8] = pack2f(c, c);
        P[9] = 0ULL;
    }
    __syncthreads();

    // ---- main eval ----
    const int gt    = blockIdx.x * TPB + t;
    const int wi0   = gt >> 1;               // strip index (2 threads/strip)
    const int khalf = t & 1;
    const bool valid = (wi0 < WPBATCH);
    const int wi = valid ? wi0 : (WPBATCH - 1);

    const int i     = wi / SPR;
    const int strip = wi - i * SPR;
    const int j0    = strip * 16;

    const float x  = (float)i * (1.0f / (NXg - 1));
    const float y0 = (float)j0 * (1.0f / (NYg - 1));
    const float y1 = (float)(j0 + 1) * (1.0f / (NYg - 1));

    const u64 xp = pack2f(x, x);
    const u64 yp = pack2f(y0, y1);

    PolyC P;
    P.C5 = pack2f(1.3333558e-3f, 1.3333558e-3f);
    P.C4 = pack2f(9.6181291e-3f, 9.6181291e-3f);
    P.C3 = pack2f(5.5504109e-2f, 5.5504109e-2f);
    P.C2 = pack2f(2.4022651e-1f, 2.4022651e-1f);
    P.C1 = pack2f(6.9314718e-1f, 6.9314718e-1f);
    P.K2EP = pack2f(-0.7213475204444817f, -0.7213475204444817f);

    u64 acc[8];
#pragma unroll
    for (int n = 0; n < 8; ++n) acc[n] = 0ULL;

    const int kbase = khalf * (KK / 2);
#pragma unroll
    for (int kk = 0; kk < KK / 2; ++kk) {
        const int k = kbase + kk;
        const ulonglong2 q0 = *reinterpret_cast<const ulonglong2*>(&sp[k * 10 + 0]); // A1,B1
        const ulonglong2 q1 = *reinterpret_cast<const ulonglong2*>(&sp[k * 10 + 2]); // A2,B2
        const ulonglong2 q2 = *reinterpret_cast<const ulonglong2*>(&sp[k * 10 + 4]); // C2,LC
        const ulonglong2 q3 = *reinterpret_cast<const ulonglong2*>(&sp[k * 10 + 6]); // G1,G0
        const u64 cP = sp[k * 10 + 8];

        u64 z1  = f2fma(xp, q0.x, q0.y);
        u64 z1s = f2mul(z1, z1);
        u64 W   = f2fma(q2.x, z1, q1.y);
        u64 z2  = f2fma(yp, q1.x, W);
        u64 m   = f2fma(z2, z2, z1s);
        u64 a0  = f2fma(m, P.K2EP, q2.y);
        u64 E   = exp2E(a0, P);
        u64 dq  = f2fma(z2, q3.x, q3.y);
        u64 r   = exp2R(dq, P);

        acc[0] = f2add(acc[0], E);
#pragma unroll
        for (int n = 1; n < 8; ++n) {
            E = f2mul(E, r);
            if (n < 7) r = f2mul(r, cP);
            acc[n] = f2add(acc[n], E);
        }
    }

    // combine the two k-halves (lanes 2s / 2s+1)
#pragma unroll
    for (int n = 0; n < 8; ++n) {
        u64 o = __shfl_xor_sync(0xFFFFFFFFu, acc[n], 1);
        acc[n] = f2add(acc[n], o);
    }

    if (valid) {
        u64* o64 = reinterpret_cast<u64*>(out);
        const size_t base = (size_t)(b * NXg + i) * (NYg / 2) + strip * 8;
        const int npairs = (strip < SPR - 1) ? 8 : 5;
        if (khalf == 0) {
#pragma unroll
            for (int n = 0; n < 4; ++n) o64[base + n] = acc[n];
        } else {
#pragma unroll
            for (int n = 4; n < 8; ++n)
                if (n < npairs) o64[base + n] = acc[n];
        }
    }
}

// ---------------------------------------------------------------------------
extern "C" void kernel_launch(void* const* d_in, const int* in_sizes, int n_in,
                              void* d_out, int out_size)
{
    const float* inp  = (const float*)d_in[0];   // [16,128]
    const float* w    = (const float*)d_in[1];   // [128,96]
    const float* bias = (const float*)d_in[2];   // [96]
    float* out = (float*)d_out;                  // [16,302,394,1]

    dim3 grid(BPBATCH, Bb);
    mdn_fused_kernel<<<grid, TPB>>>(inp, w, bias, out);
}